// round 1
// baseline (speedup 1.0000x reference)
#include <cuda_runtime.h>
#include <math.h>

// Problem constants
#define BB 2
#define NN 2048
#define DD 1024
#define HH 16
#define HD 64

// Scratch (device globals: allocation-free)
__device__ float g_Q[BB * HH * NN * HD];   // [b,h,n,hd]
__device__ float g_K[BB * HH * NN * HD];
__device__ float g_V[BB * HH * NN * HD];
__device__ float g_AO[BB * NN * DD];       // [b,n,h*hd]

// ----------------------------------------------------------------------------
// NT SGEMM: C[M x Dout] = A[M x K] * W^T, W row-major [Dout x K]
// Tiles: 128x128x16, 256 threads, 8x8 per thread (4+4 split mapping)
// ----------------------------------------------------------------------------
#define BM 128
#define BN 128
#define BKK 16
#define SAS 132   // padded smem row stride (floats), 16B-aligned rows

__global__ __launch_bounds__(256, 2)
void gemm_qkv_kernel(const float* __restrict__ X,
                     const float* __restrict__ Wq,
                     const float* __restrict__ Wk,
                     const float* __restrict__ Wv)
{
    __shared__ float As[BKK * SAS];
    __shared__ float Bs[BKK * SAS];

    const int which = blockIdx.z;
    const float* W = (which == 0) ? Wq : (which == 1) ? Wk : Wv;
    float* dst = (which == 0) ? g_Q : (which == 1) ? g_K : g_V;

    const int tid = threadIdx.x;
    const int tx = tid & 15;
    const int ty = tid >> 4;
    const int rowBase = blockIdx.y * BM;
    const int colBase = blockIdx.x * BN;

    const int lr = tid >> 2;          // 0..63
    const int lc = (tid & 3) << 2;    // 0,4,8,12

    const float* Ag = X + (size_t)(rowBase + lr) * DD + lc;
    const float* Bg = W + (size_t)(colBase + lr) * DD + lc;

    float acc[8][8];
#pragma unroll
    for (int i = 0; i < 8; i++)
#pragma unroll
        for (int j = 0; j < 8; j++) acc[i][j] = 0.0f;

    for (int k0 = 0; k0 < DD; k0 += BKK) {
        float4 a0 = *(const float4*)(Ag + k0);
        float4 a1 = *(const float4*)(Ag + (size_t)64 * DD + k0);
        float4 b0 = *(const float4*)(Bg + k0);
        float4 b1 = *(const float4*)(Bg + (size_t)64 * DD + k0);
        __syncthreads();
        As[(lc + 0) * SAS + lr] = a0.x;
        As[(lc + 1) * SAS + lr] = a0.y;
        As[(lc + 2) * SAS + lr] = a0.z;
        As[(lc + 3) * SAS + lr] = a0.w;
        As[(lc + 0) * SAS + lr + 64] = a1.x;
        As[(lc + 1) * SAS + lr + 64] = a1.y;
        As[(lc + 2) * SAS + lr + 64] = a1.z;
        As[(lc + 3) * SAS + lr + 64] = a1.w;
        Bs[(lc + 0) * SAS + lr] = b0.x;
        Bs[(lc + 1) * SAS + lr] = b0.y;
        Bs[(lc + 2) * SAS + lr] = b0.z;
        Bs[(lc + 3) * SAS + lr] = b0.w;
        Bs[(lc + 0) * SAS + lr + 64] = b1.x;
        Bs[(lc + 1) * SAS + lr + 64] = b1.y;
        Bs[(lc + 2) * SAS + lr + 64] = b1.z;
        Bs[(lc + 3) * SAS + lr + 64] = b1.w;
        __syncthreads();
#pragma unroll
        for (int kk = 0; kk < BKK; kk++) {
            float4 af0 = *(const float4*)&As[kk * SAS + ty * 4];
            float4 af1 = *(const float4*)&As[kk * SAS + 64 + ty * 4];
            float4 bf0 = *(const float4*)&Bs[kk * SAS + tx * 4];
            float4 bf1 = *(const float4*)&Bs[kk * SAS + 64 + tx * 4];
            float ar[8] = {af0.x, af0.y, af0.z, af0.w, af1.x, af1.y, af1.z, af1.w};
            float br[8] = {bf0.x, bf0.y, bf0.z, bf0.w, bf1.x, bf1.y, bf1.z, bf1.w};
#pragma unroll
            for (int i = 0; i < 8; i++)
#pragma unroll
                for (int j = 0; j < 8; j++) acc[i][j] += ar[i] * br[j];
        }
    }

    // Epilogue: scatter into [b,h,n,hd]
#pragma unroll
    for (int i = 0; i < 8; i++) {
        int r = rowBase + ((i < 4) ? (ty * 4 + i) : (64 + ty * 4 + (i - 4)));
        int b = r / NN;
        int n = r % NN;
#pragma unroll
        for (int jh = 0; jh < 2; jh++) {
            int gc = colBase + jh * 64 + tx * 4;
            int h = gc >> 6;
            int hd = gc & 63;
            float4 v = make_float4(acc[i][jh * 4 + 0], acc[i][jh * 4 + 1],
                                   acc[i][jh * 4 + 2], acc[i][jh * 4 + 3]);
            *(float4*)&dst[(((size_t)b * HH + h) * NN + n) * HD + hd] = v;
        }
    }
}

__global__ __launch_bounds__(256, 2)
void gemm_out_kernel(const float* __restrict__ W,
                     const float* __restrict__ bias,
                     float* __restrict__ out)
{
    __shared__ float As[BKK * SAS];
    __shared__ float Bs[BKK * SAS];

    const int tid = threadIdx.x;
    const int tx = tid & 15;
    const int ty = tid >> 4;
    const int rowBase = blockIdx.y * BM;
    const int colBase = blockIdx.x * BN;

    const int lr = tid >> 2;
    const int lc = (tid & 3) << 2;

    const float* Ag = g_AO + (size_t)(rowBase + lr) * DD + lc;
    const float* Bg = W + (size_t)(colBase + lr) * DD + lc;

    float acc[8][8];
#pragma unroll
    for (int i = 0; i < 8; i++)
#pragma unroll
        for (int j = 0; j < 8; j++) acc[i][j] = 0.0f;

    for (int k0 = 0; k0 < DD; k0 += BKK) {
        float4 a0 = *(const float4*)(Ag + k0);
        float4 a1 = *(const float4*)(Ag + (size_t)64 * DD + k0);
        float4 b0 = *(const float4*)(Bg + k0);
        float4 b1 = *(const float4*)(Bg + (size_t)64 * DD + k0);
        __syncthreads();
        As[(lc + 0) * SAS + lr] = a0.x;
        As[(lc + 1) * SAS + lr] = a0.y;
        As[(lc + 2) * SAS + lr] = a0.z;
        As[(lc + 3) * SAS + lr] = a0.w;
        As[(lc + 0) * SAS + lr + 64] = a1.x;
        As[(lc + 1) * SAS + lr + 64] = a1.y;
        As[(lc + 2) * SAS + lr + 64] = a1.z;
        As[(lc + 3) * SAS + lr + 64] = a1.w;
        Bs[(lc + 0) * SAS + lr] = b0.x;
        Bs[(lc + 1) * SAS + lr] = b0.y;
        Bs[(lc + 2) * SAS + lr] = b0.z;
        Bs[(lc + 3) * SAS + lr] = b0.w;
        Bs[(lc + 0) * SAS + lr + 64] = b1.x;
        Bs[(lc + 1) * SAS + lr + 64] = b1.y;
        Bs[(lc + 2) * SAS + lr + 64] = b1.z;
        Bs[(lc + 3) * SAS + lr + 64] = b1.w;
        __syncthreads();
#pragma unroll
        for (int kk = 0; kk < BKK; kk++) {
            float4 af0 = *(const float4*)&As[kk * SAS + ty * 4];
            float4 af1 = *(const float4*)&As[kk * SAS + 64 + ty * 4];
            float4 bf0 = *(const float4*)&Bs[kk * SAS + tx * 4];
            float4 bf1 = *(const float4*)&Bs[kk * SAS + 64 + tx * 4];
            float ar[8] = {af0.x, af0.y, af0.z, af0.w, af1.x, af1.y, af1.z, af1.w};
            float br[8] = {bf0.x, bf0.y, bf0.z, bf0.w, bf1.x, bf1.y, bf1.z, bf1.w};
#pragma unroll
            for (int i = 0; i < 8; i++)
#pragma unroll
                for (int j = 0; j < 8; j++) acc[i][j] += ar[i] * br[j];
        }
    }

#pragma unroll
    for (int i = 0; i < 8; i++) {
        int r = rowBase + ((i < 4) ? (ty * 4 + i) : (64 + ty * 4 + (i - 4)));
#pragma unroll
        for (int jh = 0; jh < 2; jh++) {
            int gc = colBase + jh * 64 + tx * 4;
            float4 bv = *(const float4*)&bias[gc];
            float4 v = make_float4(acc[i][jh * 4 + 0] + bv.x, acc[i][jh * 4 + 1] + bv.y,
                                   acc[i][jh * 4 + 2] + bv.z, acc[i][jh * 4 + 3] + bv.w);
            *(float4*)&out[(size_t)r * DD + gc] = v;
        }
    }
}

// ----------------------------------------------------------------------------
// Flash attention: per (b,h), 64-row q-tile, 64-key tiles, online softmax.
// smem: Qs[64][65], Kt[64(d)][68(c)] (reused as Ps[64][65]), Vs[64][64]
// 256 threads as 16x16; each thread owns a 4x4 score / 4(row)x4(d) out tile.
// ----------------------------------------------------------------------------
#define FLASH_SMEM_FLOATS (64 * 65 + 64 * 68 + 64 * 64)
#define FLASH_SMEM_BYTES (FLASH_SMEM_FLOATS * 4)

__global__ __launch_bounds__(256)
void flash_kernel()
{
    extern __shared__ float sm[];
    float* Qs = sm;                 // stride 65
    float* Kt = sm + 64 * 65;       // stride 68 (d-major), reused as Ps (stride 65)
    float* Vs = Kt + 64 * 68;       // stride 64

    const int tid = threadIdx.x;
    const int tx = tid & 15;
    const int ty = tid >> 4;
    const int bh = blockIdx.y;          // b*16 + h
    const int qb = blockIdx.x * 64;

    const float* Qg = g_Q + (size_t)bh * NN * HD + (size_t)qb * HD;
    const float* Kg = g_K + (size_t)bh * NN * HD;
    const float* Vg = g_V + (size_t)bh * NN * HD;

    for (int i = tid; i < 64 * HD; i += 256) {
        int r = i >> 6, d = i & 63;
        Qs[r * 65 + d] = Qg[i];
    }

    float m[4], l[4], acc[4][4];
#pragma unroll
    for (int i = 0; i < 4; i++) {
        m[i] = -1e30f;
        l[i] = 0.0f;
#pragma unroll
        for (int j = 0; j < 4; j++) acc[i][j] = 0.0f;
    }

    const float scale = 0.125f;  // 64^-0.5

    for (int kb = 0; kb < NN; kb += 64) {
        __syncthreads();  // previous AV reads done before overwriting Kt/Vs
        const float* Kgt = Kg + (size_t)kb * HD;
        for (int i = tid; i < 64 * HD; i += 256) {
            int c = i >> 6, d = i & 63;
            Kt[d * 68 + c] = Kgt[i];
        }
        const float4* Vg4 = (const float4*)(Vg + (size_t)kb * HD);
        for (int i = tid; i < 64 * HD / 4; i += 256) {
            ((float4*)Vs)[i] = Vg4[i];
        }
        __syncthreads();

        // Scores
        float s[4][4];
#pragma unroll
        for (int i = 0; i < 4; i++)
#pragma unroll
            for (int j = 0; j < 4; j++) s[i][j] = 0.0f;

#pragma unroll 8
        for (int d = 0; d < 64; d++) {
            float4 kv = *(const float4*)&Kt[d * 68 + tx * 4];
            float q0 = Qs[(ty * 4 + 0) * 65 + d];
            float q1 = Qs[(ty * 4 + 1) * 65 + d];
            float q2 = Qs[(ty * 4 + 2) * 65 + d];
            float q3 = Qs[(ty * 4 + 3) * 65 + d];
            s[0][0] += q0 * kv.x; s[0][1] += q0 * kv.y; s[0][2] += q0 * kv.z; s[0][3] += q0 * kv.w;
            s[1][0] += q1 * kv.x; s[1][1] += q1 * kv.y; s[1][2] += q1 * kv.z; s[1][3] += q1 * kv.w;
            s[2][0] += q2 * kv.x; s[2][1] += q2 * kv.y; s[2][2] += q2 * kv.z; s[2][3] += q2 * kv.w;
            s[3][0] += q3 * kv.x; s[3][1] += q3 * kv.y; s[3][2] += q3 * kv.z; s[3][3] += q3 * kv.w;
        }

        // Online softmax update
#pragma unroll
        for (int i = 0; i < 4; i++) {
            s[i][0] *= scale; s[i][1] *= scale; s[i][2] *= scale; s[i][3] *= scale;
            float v = fmaxf(fmaxf(s[i][0], s[i][1]), fmaxf(s[i][2], s[i][3]));
#pragma unroll
            for (int o = 8; o > 0; o >>= 1)
                v = fmaxf(v, __shfl_xor_sync(0xffffffffu, v, o));
            float mn = fmaxf(m[i], v);
            float f = __expf(m[i] - mn);
            m[i] = mn;
            l[i] *= f;
            acc[i][0] *= f; acc[i][1] *= f; acc[i][2] *= f; acc[i][3] *= f;
        }

        float rs[4];
#pragma unroll
        for (int i = 0; i < 4; i++) {
            float p0 = __expf(s[i][0] - m[i]);
            float p1 = __expf(s[i][1] - m[i]);
            float p2 = __expf(s[i][2] - m[i]);
            float p3 = __expf(s[i][3] - m[i]);
            s[i][0] = p0; s[i][1] = p1; s[i][2] = p2; s[i][3] = p3;
            rs[i] = (p0 + p1) + (p2 + p3);
        }
#pragma unroll
        for (int i = 0; i < 4; i++) {
#pragma unroll
            for (int o = 8; o > 0; o >>= 1)
                rs[i] += __shfl_xor_sync(0xffffffffu, rs[i], o);
            l[i] += rs[i];
        }

        __syncthreads();  // all threads done reading Kt (scores)
        float* Ps = Kt;   // reuse, stride 65
#pragma unroll
        for (int i = 0; i < 4; i++) {
            Ps[(ty * 4 + i) * 65 + tx * 4 + 0] = s[i][0];
            Ps[(ty * 4 + i) * 65 + tx * 4 + 1] = s[i][1];
            Ps[(ty * 4 + i) * 65 + tx * 4 + 2] = s[i][2];
            Ps[(ty * 4 + i) * 65 + tx * 4 + 3] = s[i][3];
        }
        __syncthreads();

        // acc += P @ V
#pragma unroll 8
        for (int c = 0; c < 64; c++) {
            float4 vv = *(const float4*)&Vs[c * 64 + tx * 4];
            float p0 = Ps[(ty * 4 + 0) * 65 + c];
            float p1 = Ps[(ty * 4 + 1) * 65 + c];
            float p2 = Ps[(ty * 4 + 2) * 65 + c];
            float p3 = Ps[(ty * 4 + 3) * 65 + c];
            acc[0][0] += p0 * vv.x; acc[0][1] += p0 * vv.y; acc[0][2] += p0 * vv.z; acc[0][3] += p0 * vv.w;
            acc[1][0] += p1 * vv.x; acc[1][1] += p1 * vv.y; acc[1][2] += p1 * vv.z; acc[1][3] += p1 * vv.w;
            acc[2][0] += p2 * vv.x; acc[2][1] += p2 * vv.y; acc[2][2] += p2 * vv.z; acc[2][3] += p2 * vv.w;
            acc[3][0] += p3 * vv.x; acc[3][1] += p3 * vv.y; acc[3][2] += p3 * vv.z; acc[3][3] += p3 * vv.w;
        }
    }

    // Write AO[b][n][h][hd]
    const int b = bh >> 4;
    const int h = bh & 15;
#pragma unroll
    for (int i = 0; i < 4; i++) {
        int n = qb + ty * 4 + i;
        float inv = 1.0f / l[i];
        float4 o = make_float4(acc[i][0] * inv, acc[i][1] * inv,
                               acc[i][2] * inv, acc[i][3] * inv);
        *(float4*)&g_AO[(((size_t)b * NN + n) * HH + h) * HD + tx * 4] = o;
    }
}

// ----------------------------------------------------------------------------
extern "C" void kernel_launch(void* const* d_in, const int* in_sizes, int n_in,
                              void* d_out, int out_size)
{
    const float* x  = (const float*)d_in[0];
    const float* wq = (const float*)d_in[1];
    const float* wk = (const float*)d_in[2];
    const float* wv = (const float*)d_in[3];
    const float* wo = (const float*)d_in[4];
    const float* bo = (const float*)d_in[5];
    float* out = (float*)d_out;

    cudaFuncSetAttribute(flash_kernel,
                         cudaFuncAttributeMaxDynamicSharedMemorySize,
                         FLASH_SMEM_BYTES);

    // Q,K,V projections: M=4096, N=1024, K=1024, z selects the weight
    gemm_qkv_kernel<<<dim3(8, 32, 3), 256>>>(x, wq, wk, wv);

    // Attention: 32 q-tiles x 32 (b,h)
    flash_kernel<<<dim3(32, 32), 256, FLASH_SMEM_BYTES>>>();

    // Output projection + bias
    gemm_out_kernel<<<dim3(8, 32), 256>>>(wo, bo, out);
}

// round 4
// speedup vs baseline: 3.0986x; 3.0986x over previous
#include <cuda_runtime.h>
#include <cuda_bf16.h>
#include <cstdint>
#include <math.h>

// Problem constants
#define BB 2
#define NN 2048
#define DD 1024
#define HH 16
#define HD 64
#define MTOT (BB * NN)   // 4096

// ---------------------------------------------------------------------------
// Scratch (device globals: allocation-free)
// ---------------------------------------------------------------------------
__device__ __nv_bfloat16 g_Xhi[MTOT * DD];
__device__ __nv_bfloat16 g_Xlo[MTOT * DD];
__device__ __nv_bfloat16 g_Whi[4][DD * DD];   // q,k,v,o (rows = out features)
__device__ __nv_bfloat16 g_Wlo[4][DD * DD];
__device__ __nv_bfloat16 g_Qhi[BB * HH * NN * HD];  // [b,h,n,hd]
__device__ __nv_bfloat16 g_Qlo[BB * HH * NN * HD];
__device__ __nv_bfloat16 g_Khi[BB * HH * NN * HD];
__device__ __nv_bfloat16 g_Klo[BB * HH * NN * HD];
__device__ __nv_bfloat16 g_Vhi[BB * HH * NN * HD];
__device__ __nv_bfloat16 g_Vlo[BB * HH * NN * HD];
__device__ __nv_bfloat16 g_AOhi[MTOT * DD];   // [b*n, h*hd]
__device__ __nv_bfloat16 g_AOlo[MTOT * DD];

// ---------------------------------------------------------------------------
// fp32 -> (hi, lo) bf16 split kernels
// ---------------------------------------------------------------------------
__device__ __forceinline__ void split4(const float4 v, __nv_bfloat16* hi, __nv_bfloat16* lo)
{
    __nv_bfloat16 h0 = __float2bfloat16(v.x);
    __nv_bfloat16 h1 = __float2bfloat16(v.y);
    __nv_bfloat16 h2 = __float2bfloat16(v.z);
    __nv_bfloat16 h3 = __float2bfloat16(v.w);
    __nv_bfloat16 l0 = __float2bfloat16(v.x - __bfloat162float(h0));
    __nv_bfloat16 l1 = __float2bfloat16(v.y - __bfloat162float(h1));
    __nv_bfloat16 l2 = __float2bfloat16(v.z - __bfloat162float(h2));
    __nv_bfloat16 l3 = __float2bfloat16(v.w - __bfloat162float(h3));
    reinterpret_cast<__nv_bfloat162*>(hi)[0] = __nv_bfloat162(h0, h1);
    reinterpret_cast<__nv_bfloat162*>(hi)[1] = __nv_bfloat162(h2, h3);
    reinterpret_cast<__nv_bfloat162*>(lo)[0] = __nv_bfloat162(l0, l1);
    reinterpret_cast<__nv_bfloat162*>(lo)[1] = __nv_bfloat162(l2, l3);
}

__global__ void split_x_kernel(const float* __restrict__ x)
{
    int i = (blockIdx.x * blockDim.x + threadIdx.x) * 4;
    float4 v = *(const float4*)(x + i);
    split4(v, &g_Xhi[i], &g_Xlo[i]);
}

__global__ void split_w_kernel(const float* __restrict__ w, int which)
{
    int i = (blockIdx.x * blockDim.x + threadIdx.x) * 4;
    float4 v = *(const float4*)(w + i);
    split4(v, &g_Whi[which][i], &g_Wlo[which][i]);
}

// ---------------------------------------------------------------------------
// MMA / ldmatrix / cp.async primitives (all legal on plain sm_103 PTX target)
// ---------------------------------------------------------------------------
__device__ __forceinline__ uint32_t s2u(const void* p)
{
    uint32_t a;
    asm("{ .reg .u64 t; cvta.to.shared.u64 t, %1; cvt.u32.u64 %0, t; }" : "=r"(a) : "l"(p));
    return a;
}

__device__ __forceinline__ void mma_bf16(float* c, const uint32_t* a, uint32_t b0, uint32_t b1)
{
    asm volatile(
        "mma.sync.aligned.m16n8k16.row.col.f32.bf16.bf16.f32 "
        "{%0,%1,%2,%3}, {%4,%5,%6,%7}, {%8,%9}, {%0,%1,%2,%3};"
        : "+f"(c[0]), "+f"(c[1]), "+f"(c[2]), "+f"(c[3])
        : "r"(a[0]), "r"(a[1]), "r"(a[2]), "r"(a[3]), "r"(b0), "r"(b1));
}

__device__ __forceinline__ void ldmx4(uint32_t* r, uint32_t a)
{
    asm volatile("ldmatrix.sync.aligned.m8n8.x4.shared.b16 {%0,%1,%2,%3}, [%4];"
                 : "=r"(r[0]), "=r"(r[1]), "=r"(r[2]), "=r"(r[3]) : "r"(a));
}

__device__ __forceinline__ void ldmx4t(uint32_t* r, uint32_t a)
{
    asm volatile("ldmatrix.sync.aligned.m8n8.x4.trans.shared.b16 {%0,%1,%2,%3}, [%4];"
                 : "=r"(r[0]), "=r"(r[1]), "=r"(r[2]), "=r"(r[3]) : "r"(a));
}

#define CP16(dst, src) asm volatile("cp.async.cg.shared.global [%0], [%1], 16;" :: "r"(dst), "l"(src))
#define CPCOMMIT() asm volatile("cp.async.commit_group;" ::: "memory")
#define CPWAIT(n) asm volatile("cp.async.wait_group %0;" :: "n"(n) : "memory")

// SW128-style tile addressing: tile rows = 64 bf16 = 128B; 8-row groups = 1024B.
__device__ __forceinline__ uint32_t tile_addr(uint32_t tbase, int row, int chunk)
{
    return tbase + ((row >> 3) << 10) + ((row & 7) << 7) + (((chunk ^ (row & 7))) << 4);
}

__device__ __forceinline__ uint32_t pack_bf16(float a, float b)
{
    __nv_bfloat162 p = __float22bfloat162_rn(make_float2(a, b));
    return *reinterpret_cast<uint32_t*>(&p);
}

__device__ __forceinline__ uint32_t residual_pack(uint32_t hi, float a, float b)
{
    float r0 = a - __bfloat162float(__ushort_as_bfloat16((unsigned short)(hi & 0xffff)));
    float r1 = b - __bfloat162float(__ushort_as_bfloat16((unsigned short)(hi >> 16)));
    return pack_bf16(r0, r1);
}

// ---------------------------------------------------------------------------
// Split-bf16 NT GEMM on mma.sync: C[4096x1024] = A @ W^T, K = 1024.
// 3-term: Ahi*Bhi + Ahi*Blo + Alo*Bhi, fp32 accumulators.
// Block 256 thr (8 warps, 4m x 2n), tile 128x128, K-chunk 64, double buffer.
// ---------------------------------------------------------------------------
#define G_TILE 16384                      // 128 rows x 128B
#define G_STAGE (4 * G_TILE)              // Ahi, Alo, Bhi, Blo
#define G_SMEM (2 * G_STAGE)              // 131072

__global__ __launch_bounds__(256, 1)
void gemm_mma_kernel(int is_out, float* __restrict__ outp, const float* __restrict__ bias)
{
    extern __shared__ char smem[];
    const uint32_t sb = s2u(smem);
    const int tid = threadIdx.x;
    const int lane = tid & 31;
    const int wid = tid >> 5;
    const int wm = wid >> 1;          // 0..3
    const int wn = wid & 1;           // 0..1
    const int rb = blockIdx.y * 128;
    const int cb = blockIdx.x * 128;
    const int which = is_out ? 3 : blockIdx.z;

    const __nv_bfloat16* __restrict__ Ahi = is_out ? g_AOhi : g_Xhi;
    const __nv_bfloat16* __restrict__ Alo = is_out ? g_AOlo : g_Xlo;
    const __nv_bfloat16* __restrict__ Bhi = g_Whi[which];
    const __nv_bfloat16* __restrict__ Blo = g_Wlo[which];

    float acc[2][8][4];
#pragma unroll
    for (int i = 0; i < 2; i++)
#pragma unroll
        for (int j = 0; j < 8; j++)
#pragma unroll
            for (int q = 0; q < 4; q++) acc[i][j][q] = 0.0f;

    auto issue = [&](int kc) {
        const int k0 = kc * 64;
        const uint32_t stage = sb + (kc & 1) * G_STAGE;
#pragma unroll
        for (int it = 0; it < 16; it++) {
            int idx = tid + it * 256;
            int m = idx >> 10;
            int rem = idx & 1023;
            int row = rem >> 3;
            int c = rem & 7;
            const __nv_bfloat16* src;
            if (m == 0)      src = Ahi + (size_t)(rb + row) * DD + k0 + c * 8;
            else if (m == 1) src = Alo + (size_t)(rb + row) * DD + k0 + c * 8;
            else if (m == 2) src = Bhi + (size_t)(cb + row) * DD + k0 + c * 8;
            else             src = Blo + (size_t)(cb + row) * DD + k0 + c * 8;
            CP16(tile_addr(stage + m * G_TILE, row, c), src);
        }
        CPCOMMIT();
    };

    issue(0);

    const int mi = lane >> 3;
    const int rw = lane & 7;

    for (int kc = 0; kc < 16; kc++) {
        __syncthreads();
        if (kc < 15) { issue(kc + 1); CPWAIT(1); }
        else         { CPWAIT(0); }
        __syncthreads();

        const uint32_t stage = sb + (kc & 1) * G_STAGE;
        const uint32_t AHI = stage, ALO = stage + G_TILE;
        const uint32_t BHI = stage + 2 * G_TILE, BLO = stage + 3 * G_TILE;

#pragma unroll
        for (int ks = 0; ks < 4; ks++) {
            uint32_t ahi[2][4], alo[2][4];
#pragma unroll
            for (int i = 0; i < 2; i++) {
                int row = wm * 32 + i * 16 + ((mi & 1) << 3) + rw;
                int ch = ks * 2 + (mi >> 1);
                ldmx4(ahi[i], tile_addr(AHI, row, ch));
                ldmx4(alo[i], tile_addr(ALO, row, ch));
            }
#pragma unroll
            for (int jj = 0; jj < 4; jj++) {
                int brow = wn * 64 + jj * 16 + ((mi >> 1) << 3) + rw;
                int bch = ks * 2 + (mi & 1);
                uint32_t bhi[4], blo[4];
                ldmx4(bhi, tile_addr(BHI, brow, bch));
                ldmx4(blo, tile_addr(BLO, brow, bch));
#pragma unroll
                for (int i = 0; i < 2; i++) {
                    mma_bf16(acc[i][2 * jj],     ahi[i], bhi[0], bhi[1]);
                    mma_bf16(acc[i][2 * jj],     ahi[i], blo[0], blo[1]);
                    mma_bf16(acc[i][2 * jj],     alo[i], bhi[0], bhi[1]);
                    mma_bf16(acc[i][2 * jj + 1], ahi[i], bhi[2], bhi[3]);
                    mma_bf16(acc[i][2 * jj + 1], ahi[i], blo[2], blo[3]);
                    mma_bf16(acc[i][2 * jj + 1], alo[i], bhi[2], bhi[3]);
                }
            }
        }
    }

    // Epilogue
#pragma unroll
    for (int i = 0; i < 2; i++) {
#pragma unroll
        for (int j = 0; j < 8; j++) {
            int col = cb + wn * 64 + j * 8 + (lane & 3) * 2;
            int r0 = rb + wm * 32 + i * 16 + (lane >> 2);
            int r1 = r0 + 8;
            if (!is_out) {
                __nv_bfloat16* dhi = (which == 0) ? g_Qhi : (which == 1) ? g_Khi : g_Vhi;
                __nv_bfloat16* dlo = (which == 0) ? g_Qlo : (which == 1) ? g_Klo : g_Vlo;
                int h = col >> 6, hd = col & 63;
#pragma unroll
                for (int half = 0; half < 2; half++) {
                    int r = half ? r1 : r0;
                    float v0 = acc[i][j][half * 2 + 0];
                    float v1 = acc[i][j][half * 2 + 1];
                    int b = r >> 11, n = r & 2047;
                    size_t di = (((size_t)b * HH + h) * NN + n) * HD + hd;
                    uint32_t phi = pack_bf16(v0, v1);
                    uint32_t plo = residual_pack(phi, v0, v1);
                    *reinterpret_cast<uint32_t*>(&dhi[di]) = phi;
                    *reinterpret_cast<uint32_t*>(&dlo[di]) = plo;
                }
            } else {
                float2 bv = *(const float2*)&bias[col];
#pragma unroll
                for (int half = 0; half < 2; half++) {
                    int r = half ? r1 : r0;
                    float2 v = make_float2(acc[i][j][half * 2 + 0] + bv.x,
                                           acc[i][j][half * 2 + 1] + bv.y);
                    *(float2*)&outp[(size_t)r * DD + col] = v;
                }
            }
        }
    }
}

// ---------------------------------------------------------------------------
// Flash attention on mma.sync.
// Block 128 thr (4 warps, 16 q-rows each), q-tile 64, key-tile 64, 2 stages.
// S = 3-term split(Q,K); PV = 3-term split(P,V) (Plo*Vlo dropped, ~4e-6).
// smem: Qhi, Qlo | stage{Khi, Klo, Vhi, Vlo} x2  => 10 tiles = 80 KB
// ---------------------------------------------------------------------------
#define F_TILE 8192
#define F_STAGE (4 * F_TILE)
#define F_SMEM (2 * F_TILE + 2 * F_STAGE)   // 81920

__global__ __launch_bounds__(128, 2)
void flash_mma_kernel()
{
    extern __shared__ char smem[];
    const uint32_t sb = s2u(smem);
    const int tid = threadIdx.x;
    const int lane = tid & 31;
    const int w = tid >> 5;
    const int bh = blockIdx.y;
    const int qb = blockIdx.x * 64;
    const int b = bh >> 4, h = bh & 15;

    const size_t bhbase = (size_t)bh * NN * HD;
    const __nv_bfloat16* Qhig = g_Qhi + bhbase + (size_t)qb * HD;
    const __nv_bfloat16* Qlog = g_Qlo + bhbase + (size_t)qb * HD;

    // Prologue: load Q (2 tiles x 512 chunks)
#pragma unroll
    for (int it = 0; it < 8; it++) {
        int idx = tid + it * 128;
        int m = idx >> 9;
        int rem = idx & 511;
        int row = rem >> 3, c = rem & 7;
        const __nv_bfloat16* src = (m ? Qlog : Qhig) + row * HD + c * 8;
        CP16(tile_addr(sb + m * F_TILE, row, c), src);
    }
    CPCOMMIT();

    auto issue_kv = [&](int kt) {
        const uint32_t stage = sb + 2 * F_TILE + (kt & 1) * F_STAGE;
        const size_t kvoff = bhbase + (size_t)kt * 64 * HD;
#pragma unroll
        for (int it = 0; it < 16; it++) {
            int idx = tid + it * 128;
            int m = idx >> 9;
            int rem = idx & 511;
            int row = rem >> 3, c = rem & 7;
            const __nv_bfloat16* src =
                (m == 0 ? g_Khi : m == 1 ? g_Klo : m == 2 ? g_Vhi : g_Vlo)
                + kvoff + row * HD + c * 8;
            CP16(tile_addr(stage + m * F_TILE, row, c), src);
        }
        CPCOMMIT();
    };

    issue_kv(0);
    CPWAIT(0);
    __syncthreads();

    const int mi = lane >> 3;
    const int rw = lane & 7;

    // Q fragments, kept in registers for the whole kernel
    uint32_t qhi[4][4], qlo[4][4];
#pragma unroll
    for (int ks = 0; ks < 4; ks++) {
        int row = w * 16 + ((mi & 1) << 3) + rw;
        int ch = ks * 2 + (mi >> 1);
        ldmx4(qhi[ks], tile_addr(sb, row, ch));
        ldmx4(qlo[ks], tile_addr(sb + F_TILE, row, ch));
    }

    float m0 = -1e30f, m1 = -1e30f, l0 = 0.0f, l1 = 0.0f;
    float o[8][4];
#pragma unroll
    for (int j = 0; j < 8; j++)
#pragma unroll
        for (int q = 0; q < 4; q++) o[j][q] = 0.0f;

    const float scale = 0.125f;

    for (int kt = 0; kt < 32; kt++) {
        __syncthreads();
        if (kt < 31) { issue_kv(kt + 1); CPWAIT(1); }
        else         { CPWAIT(0); }
        __syncthreads();

        const uint32_t stage = sb + 2 * F_TILE + (kt & 1) * F_STAGE;
        const uint32_t KHI = stage, KLO = stage + F_TILE;
        const uint32_t VHI = stage + 2 * F_TILE, VLO = stage + 3 * F_TILE;

        // S = Q @ K^T (3-term split)
        float s[8][4];
#pragma unroll
        for (int j = 0; j < 8; j++)
#pragma unroll
            for (int q = 0; q < 4; q++) s[j][q] = 0.0f;

#pragma unroll
        for (int ks = 0; ks < 4; ks++) {
#pragma unroll
            for (int jj = 0; jj < 4; jj++) {
                int brow = jj * 16 + ((mi >> 1) << 3) + rw;
                int bch = ks * 2 + (mi & 1);
                uint32_t khi[4], klo[4];
                ldmx4(khi, tile_addr(KHI, brow, bch));
                ldmx4(klo, tile_addr(KLO, brow, bch));
                mma_bf16(s[2 * jj],     qhi[ks], khi[0], khi[1]);
                mma_bf16(s[2 * jj],     qhi[ks], klo[0], klo[1]);
                mma_bf16(s[2 * jj],     qlo[ks], khi[0], khi[1]);
                mma_bf16(s[2 * jj + 1], qhi[ks], khi[2], khi[3]);
                mma_bf16(s[2 * jj + 1], qhi[ks], klo[2], klo[3]);
                mma_bf16(s[2 * jj + 1], qlo[ks], khi[2], khi[3]);
            }
        }

        // online softmax
        float rm0 = -1e30f, rm1 = -1e30f;
#pragma unroll
        for (int j = 0; j < 8; j++) {
#pragma unroll
            for (int q = 0; q < 4; q++) s[j][q] *= scale;
            rm0 = fmaxf(rm0, fmaxf(s[j][0], s[j][1]));
            rm1 = fmaxf(rm1, fmaxf(s[j][2], s[j][3]));
        }
        rm0 = fmaxf(rm0, __shfl_xor_sync(0xffffffffu, rm0, 1));
        rm0 = fmaxf(rm0, __shfl_xor_sync(0xffffffffu, rm0, 2));
        rm1 = fmaxf(rm1, __shfl_xor_sync(0xffffffffu, rm1, 1));
        rm1 = fmaxf(rm1, __shfl_xor_sync(0xffffffffu, rm1, 2));

        float nm0 = fmaxf(m0, rm0), nm1 = fmaxf(m1, rm1);
        float f0 = __expf(m0 - nm0), f1 = __expf(m1 - nm1);
        m0 = nm0; m1 = nm1;
#pragma unroll
        for (int j = 0; j < 8; j++) {
            o[j][0] *= f0; o[j][1] *= f0; o[j][2] *= f1; o[j][3] *= f1;
        }

        float rs0 = 0.0f, rs1 = 0.0f;
#pragma unroll
        for (int j = 0; j < 8; j++) {
            s[j][0] = __expf(s[j][0] - m0);
            s[j][1] = __expf(s[j][1] - m0);
            s[j][2] = __expf(s[j][2] - m1);
            s[j][3] = __expf(s[j][3] - m1);
            rs0 += s[j][0] + s[j][1];
            rs1 += s[j][2] + s[j][3];
        }
        rs0 += __shfl_xor_sync(0xffffffffu, rs0, 1);
        rs0 += __shfl_xor_sync(0xffffffffu, rs0, 2);
        rs1 += __shfl_xor_sync(0xffffffffu, rs1, 1);
        rs1 += __shfl_xor_sync(0xffffffffu, rs1, 2);
        l0 = l0 * f0 + rs0;
        l1 = l1 * f1 + rs1;

        // P fragments: hi + residual lo (2-term split of P)
        uint32_t pa[4][4], pl[4][4];
#pragma unroll
        for (int kk = 0; kk < 4; kk++) {
            pa[kk][0] = pack_bf16(s[2 * kk][0],     s[2 * kk][1]);
            pa[kk][1] = pack_bf16(s[2 * kk][2],     s[2 * kk][3]);
            pa[kk][2] = pack_bf16(s[2 * kk + 1][0], s[2 * kk + 1][1]);
            pa[kk][3] = pack_bf16(s[2 * kk + 1][2], s[2 * kk + 1][3]);
            pl[kk][0] = residual_pack(pa[kk][0], s[2 * kk][0],     s[2 * kk][1]);
            pl[kk][1] = residual_pack(pa[kk][1], s[2 * kk][2],     s[2 * kk][3]);
            pl[kk][2] = residual_pack(pa[kk][2], s[2 * kk + 1][0], s[2 * kk + 1][1]);
            pl[kk][3] = residual_pack(pa[kk][3], s[2 * kk + 1][2], s[2 * kk + 1][3]);
        }

        // O += P @ V (3-term: Phi*Vhi + Phi*Vlo + Plo*Vhi)
#pragma unroll
        for (int kk = 0; kk < 4; kk++) {
#pragma unroll
            for (int jj = 0; jj < 4; jj++) {
                int vrow = kk * 16 + ((mi & 1) << 3) + rw;
                int vch = jj * 2 + (mi >> 1);
                uint32_t vh[4], vl[4];
                ldmx4t(vh, tile_addr(VHI, vrow, vch));
                ldmx4t(vl, tile_addr(VLO, vrow, vch));
                mma_bf16(o[2 * jj],     pa[kk], vh[0], vh[1]);
                mma_bf16(o[2 * jj],     pa[kk], vl[0], vl[1]);
                mma_bf16(o[2 * jj],     pl[kk], vh[0], vh[1]);
                mma_bf16(o[2 * jj + 1], pa[kk], vh[2], vh[3]);
                mma_bf16(o[2 * jj + 1], pa[kk], vl[2], vl[3]);
                mma_bf16(o[2 * jj + 1], pl[kk], vh[2], vh[3]);
            }
        }
    }

    // Epilogue: AO[b*n][h*64+d] as bf16 hi/lo
    float inv0 = 1.0f / l0, inv1 = 1.0f / l1;
    int r0 = qb + w * 16 + (lane >> 2);
    int r1 = r0 + 8;
    size_t row0 = (size_t)b * NN + r0;
    size_t row1 = (size_t)b * NN + r1;
#pragma unroll
    for (int j = 0; j < 8; j++) {
        int col = h * 64 + j * 8 + (lane & 3) * 2;
#pragma unroll
        for (int half = 0; half < 2; half++) {
            float v0 = o[j][half * 2 + 0] * (half ? inv1 : inv0);
            float v1 = o[j][half * 2 + 1] * (half ? inv1 : inv0);
            size_t ri = (half ? row1 : row0) * DD + col;
            uint32_t phi = pack_bf16(v0, v1);
            uint32_t plo = residual_pack(phi, v0, v1);
            *reinterpret_cast<uint32_t*>(&g_AOhi[ri]) = phi;
            *reinterpret_cast<uint32_t*>(&g_AOlo[ri]) = plo;
        }
    }
}

// ----------------------------------------------------------------------------
extern "C" void kernel_launch(void* const* d_in, const int* in_sizes, int n_in,
                              void* d_out, int out_size)
{
    const float* x  = (const float*)d_in[0];
    const float* wq = (const float*)d_in[1];
    const float* wk = (const float*)d_in[2];
    const float* wv = (const float*)d_in[3];
    const float* wo = (const float*)d_in[4];
    const float* bo = (const float*)d_in[5];
    float* out = (float*)d_out;

    cudaFuncSetAttribute(gemm_mma_kernel,
                         cudaFuncAttributeMaxDynamicSharedMemorySize, G_SMEM);
    cudaFuncSetAttribute(flash_mma_kernel,
                         cudaFuncAttributeMaxDynamicSharedMemorySize, F_SMEM);

    // Split fp32 -> bf16 hi/lo
    split_x_kernel<<<4096, 256>>>(x);
    split_w_kernel<<<1024, 256>>>(wq, 0);
    split_w_kernel<<<1024, 256>>>(wk, 1);
    split_w_kernel<<<1024, 256>>>(wv, 2);
    split_w_kernel<<<1024, 256>>>(wo, 3);

    // QKV projections (z selects weight; epilogue writes Q/K/V bf16 hi/lo)
    gemm_mma_kernel<<<dim3(8, 32, 3), 256, G_SMEM>>>(0, nullptr, nullptr);

    // Attention (writes AO bf16 hi/lo)
    flash_mma_kernel<<<dim3(32, 32), 128, F_SMEM>>>();

    // Output projection + bias (fp32 out)
    gemm_mma_kernel<<<dim3(8, 32, 1), 256, G_SMEM>>>(1, out, bo);
}

// round 5
// speedup vs baseline: 3.1123x; 1.0044x over previous
#include <cuda_runtime.h>
#include <cuda_bf16.h>
#include <cstdint>
#include <math.h>

// Problem constants
#define BB 2
#define NN 2048
#define DD 1024
#define HH 16
#define HD 64
#define MTOT (BB * NN)   // 4096

// ---------------------------------------------------------------------------
// Scratch (device globals: allocation-free)
// ---------------------------------------------------------------------------
__device__ __nv_bfloat16 g_Xhi[MTOT * DD];
__device__ __nv_bfloat16 g_Xlo[MTOT * DD];
__device__ __nv_bfloat16 g_Whi[4][DD * DD];   // q,k,v,o (rows = out features)
__device__ __nv_bfloat16 g_Wlo[4][DD * DD];
__device__ __nv_bfloat16 g_Qhi[BB * HH * NN * HD];  // [b,h,n,hd]
__device__ __nv_bfloat16 g_Qlo[BB * HH * NN * HD];
__device__ __nv_bfloat16 g_Khi[BB * HH * NN * HD];
__device__ __nv_bfloat16 g_Klo[BB * HH * NN * HD];
__device__ __nv_bfloat16 g_Vhi[BB * HH * NN * HD];
__device__ __nv_bfloat16 g_Vlo[BB * HH * NN * HD];
__device__ __nv_bfloat16 g_AOhi[MTOT * DD];   // [b*n, h*hd]
__device__ __nv_bfloat16 g_AOlo[MTOT * DD];

// ---------------------------------------------------------------------------
// fp32 -> (hi, lo) bf16 split kernels
// ---------------------------------------------------------------------------
__device__ __forceinline__ void split4(const float4 v, __nv_bfloat16* hi, __nv_bfloat16* lo)
{
    __nv_bfloat16 h0 = __float2bfloat16(v.x);
    __nv_bfloat16 h1 = __float2bfloat16(v.y);
    __nv_bfloat16 h2 = __float2bfloat16(v.z);
    __nv_bfloat16 h3 = __float2bfloat16(v.w);
    __nv_bfloat16 l0 = __float2bfloat16(v.x - __bfloat162float(h0));
    __nv_bfloat16 l1 = __float2bfloat16(v.y - __bfloat162float(h1));
    __nv_bfloat16 l2 = __float2bfloat16(v.z - __bfloat162float(h2));
    __nv_bfloat16 l3 = __float2bfloat16(v.w - __bfloat162float(h3));
    reinterpret_cast<__nv_bfloat162*>(hi)[0] = __nv_bfloat162(h0, h1);
    reinterpret_cast<__nv_bfloat162*>(hi)[1] = __nv_bfloat162(h2, h3);
    reinterpret_cast<__nv_bfloat162*>(lo)[0] = __nv_bfloat162(l0, l1);
    reinterpret_cast<__nv_bfloat162*>(lo)[1] = __nv_bfloat162(l2, l3);
}

__global__ void split_x_kernel(const float* __restrict__ x)
{
    int i = (blockIdx.x * blockDim.x + threadIdx.x) * 4;
    float4 v = *(const float4*)(x + i);
    split4(v, &g_Xhi[i], &g_Xlo[i]);
}

__global__ void split_w_kernel(const float* __restrict__ wq, const float* __restrict__ wk,
                               const float* __restrict__ wv, const float* __restrict__ wo)
{
    const float* w = (blockIdx.y == 0) ? wq : (blockIdx.y == 1) ? wk
                   : (blockIdx.y == 2) ? wv : wo;
    int i = (blockIdx.x * blockDim.x + threadIdx.x) * 4;
    float4 v = *(const float4*)(w + i);
    split4(v, &g_Whi[blockIdx.y][i], &g_Wlo[blockIdx.y][i]);
}

// ---------------------------------------------------------------------------
// MMA / ldmatrix / cp.async primitives
// ---------------------------------------------------------------------------
__device__ __forceinline__ uint32_t s2u(const void* p)
{
    uint32_t a;
    asm("{ .reg .u64 t; cvta.to.shared.u64 t, %1; cvt.u32.u64 %0, t; }" : "=r"(a) : "l"(p));
    return a;
}

__device__ __forceinline__ void mma_bf16(float* c, const uint32_t* a, uint32_t b0, uint32_t b1)
{
    asm volatile(
        "mma.sync.aligned.m16n8k16.row.col.f32.bf16.bf16.f32 "
        "{%0,%1,%2,%3}, {%4,%5,%6,%7}, {%8,%9}, {%0,%1,%2,%3};"
        : "+f"(c[0]), "+f"(c[1]), "+f"(c[2]), "+f"(c[3])
        : "r"(a[0]), "r"(a[1]), "r"(a[2]), "r"(a[3]), "r"(b0), "r"(b1));
}

__device__ __forceinline__ void ldmx4(uint32_t* r, uint32_t a)
{
    asm volatile("ldmatrix.sync.aligned.m8n8.x4.shared.b16 {%0,%1,%2,%3}, [%4];"
                 : "=r"(r[0]), "=r"(r[1]), "=r"(r[2]), "=r"(r[3]) : "r"(a));
}

__device__ __forceinline__ void ldmx4t(uint32_t* r, uint32_t a)
{
    asm volatile("ldmatrix.sync.aligned.m8n8.x4.trans.shared.b16 {%0,%1,%2,%3}, [%4];"
                 : "=r"(r[0]), "=r"(r[1]), "=r"(r[2]), "=r"(r[3]) : "r"(a));
}

#define CP16(dst, src) asm volatile("cp.async.cg.shared.global [%0], [%1], 16;" :: "r"(dst), "l"(src))
#define CPCOMMIT() asm volatile("cp.async.commit_group;" ::: "memory")
#define CPWAIT(n) asm volatile("cp.async.wait_group %0;" :: "n"(n) : "memory")

// Swizzled tile addressing: rows of 64 bf16 (128B), 8-row groups of 1024B.
__device__ __forceinline__ uint32_t tile_addr(uint32_t tbase, int row, int chunk)
{
    return tbase + ((row >> 3) << 10) + ((row & 7) << 7) + (((chunk ^ (row & 7))) << 4);
}

__device__ __forceinline__ uint32_t pack_bf16(float a, float b)
{
    __nv_bfloat162 p = __float22bfloat162_rn(make_float2(a, b));
    return *reinterpret_cast<uint32_t*>(&p);
}

__device__ __forceinline__ uint32_t residual_pack(uint32_t hi, float a, float b)
{
    float r0 = a - __bfloat162float(__ushort_as_bfloat16((unsigned short)(hi & 0xffff)));
    float r1 = b - __bfloat162float(__ushort_as_bfloat16((unsigned short)(hi >> 16)));
    return pack_bf16(r0, r1);
}

// ---------------------------------------------------------------------------
// Split-bf16 NT GEMM: C = A @ W^T, K=1024, 3-term compensation.
// CTA tile 256x128, 8 warps (4m x 2n), warp tile 64x64, K-chunk 64, 2 stages.
// ---------------------------------------------------------------------------
#define G_ATILE 32768                    // 256 rows x 128B
#define G_BTILE 16384                    // 128 rows x 128B
#define G_STAGE (2 * G_ATILE + 2 * G_BTILE)   // 98304
#define G_SMEM (2 * G_STAGE)             // 196608

__global__ __launch_bounds__(256, 1)
void gemm_mma_kernel(int is_out, float* __restrict__ outp, const float* __restrict__ bias)
{
    extern __shared__ char smem[];
    const uint32_t sb = s2u(smem);
    const int tid = threadIdx.x;
    const int lane = tid & 31;
    const int wid = tid >> 5;
    const int wm = wid >> 1;          // 0..3 -> 64-row group
    const int wn = wid & 1;           // 0..1 -> 64-col group
    const int rb = blockIdx.y * 256;
    const int cb = blockIdx.x * 128;
    const int which = is_out ? 3 : blockIdx.z;

    const __nv_bfloat16* __restrict__ Ahi = is_out ? g_AOhi : g_Xhi;
    const __nv_bfloat16* __restrict__ Alo = is_out ? g_AOlo : g_Xlo;
    const __nv_bfloat16* __restrict__ Bhi = g_Whi[which];
    const __nv_bfloat16* __restrict__ Blo = g_Wlo[which];

    float acc[4][8][4];
#pragma unroll
    for (int i = 0; i < 4; i++)
#pragma unroll
        for (int j = 0; j < 8; j++)
#pragma unroll
            for (int q = 0; q < 4; q++) acc[i][j][q] = 0.0f;

    // 6144 16B-chunks per stage: A hi/lo 2048 each, B hi/lo 1024 each.
    auto issue = [&](int kc) {
        const int k0 = kc * 64;
        const uint32_t stage = sb + (kc & 1) * G_STAGE;
#pragma unroll
        for (int it = 0; it < 24; it++) {
            int idx = tid + it * 256;
            const __nv_bfloat16* src;
            uint32_t base;
            int row, c;
            if (idx < 4096) {
                int m = idx >> 11;
                int rem = idx & 2047;
                row = rem >> 3; c = rem & 7;
                src = (m ? Alo : Ahi) + (size_t)(rb + row) * DD + k0 + c * 8;
                base = stage + m * G_ATILE;
            } else {
                int idx2 = idx - 4096;
                int m = idx2 >> 10;
                int rem = idx2 & 1023;
                row = rem >> 3; c = rem & 7;
                src = (m ? Blo : Bhi) + (size_t)(cb + row) * DD + k0 + c * 8;
                base = stage + 2 * G_ATILE + m * G_BTILE;
            }
            CP16(tile_addr(base, row, c), src);
        }
        CPCOMMIT();
    };

    issue(0);

    const int mi = lane >> 3;
    const int rw = lane & 7;

    for (int kc = 0; kc < 16; kc++) {
        __syncthreads();
        if (kc < 15) { issue(kc + 1); CPWAIT(1); }
        else         { CPWAIT(0); }
        __syncthreads();

        const uint32_t stage = sb + (kc & 1) * G_STAGE;
        const uint32_t AHI = stage, ALO = stage + G_ATILE;
        const uint32_t BHI = stage + 2 * G_ATILE, BLO = BHI + G_BTILE;

#pragma unroll
        for (int ks = 0; ks < 4; ks++) {
            uint32_t ahi[4][4], alo[4][4];
#pragma unroll
            for (int mt = 0; mt < 4; mt++) {
                int row = wm * 64 + mt * 16 + ((mi & 1) << 3) + rw;
                int ch = ks * 2 + (mi >> 1);
                ldmx4(ahi[mt], tile_addr(AHI, row, ch));
                ldmx4(alo[mt], tile_addr(ALO, row, ch));
            }
#pragma unroll
            for (int jj = 0; jj < 4; jj++) {
                int brow = wn * 64 + jj * 16 + ((mi >> 1) << 3) + rw;
                int bch = ks * 2 + (mi & 1);
                uint32_t bhi[4], blo[4];
                ldmx4(bhi, tile_addr(BHI, brow, bch));
                ldmx4(blo, tile_addr(BLO, brow, bch));
#pragma unroll
                for (int mt = 0; mt < 4; mt++) {
                    mma_bf16(acc[mt][2 * jj],     ahi[mt], bhi[0], bhi[1]);
                    mma_bf16(acc[mt][2 * jj],     ahi[mt], blo[0], blo[1]);
                    mma_bf16(acc[mt][2 * jj],     alo[mt], bhi[0], bhi[1]);
                    mma_bf16(acc[mt][2 * jj + 1], ahi[mt], bhi[2], bhi[3]);
                    mma_bf16(acc[mt][2 * jj + 1], ahi[mt], blo[2], blo[3]);
                    mma_bf16(acc[mt][2 * jj + 1], alo[mt], bhi[2], bhi[3]);
                }
            }
        }
    }

    // Epilogue
#pragma unroll
    for (int mt = 0; mt < 4; mt++) {
#pragma unroll
        for (int j = 0; j < 8; j++) {
            int col = cb + wn * 64 + j * 8 + (lane & 3) * 2;
            int r0 = rb + wm * 64 + mt * 16 + (lane >> 2);
            int r1 = r0 + 8;
            if (!is_out) {
                __nv_bfloat16* dhi = (which == 0) ? g_Qhi : (which == 1) ? g_Khi : g_Vhi;
                __nv_bfloat16* dlo = (which == 0) ? g_Qlo : (which == 1) ? g_Klo : g_Vlo;
                int h = col >> 6, hd = col & 63;
#pragma unroll
                for (int half = 0; half < 2; half++) {
                    int r = half ? r1 : r0;
                    float v0 = acc[mt][j][half * 2 + 0];
                    float v1 = acc[mt][j][half * 2 + 1];
                    int b = r >> 11, n = r & 2047;
                    size_t di = (((size_t)b * HH + h) * NN + n) * HD + hd;
                    uint32_t phi = pack_bf16(v0, v1);
                    uint32_t plo = residual_pack(phi, v0, v1);
                    *reinterpret_cast<uint32_t*>(&dhi[di]) = phi;
                    *reinterpret_cast<uint32_t*>(&dlo[di]) = plo;
                }
            } else {
                float2 bv = *(const float2*)&bias[col];
#pragma unroll
                for (int half = 0; half < 2; half++) {
                    int r = half ? r1 : r0;
                    float2 v = make_float2(acc[mt][j][half * 2 + 0] + bv.x,
                                           acc[mt][j][half * 2 + 1] + bv.y);
                    *(float2*)&outp[(size_t)r * DD + col] = v;
                }
            }
        }
    }
}

// ---------------------------------------------------------------------------
// Flash attention: q-tile 128, 4 warps x 32 q-rows (2 m16 tiles), key-tile 64,
// double-buffered KV. S and PV both 3-term split. smem = 96 KB, 2 CTAs/SM.
// ---------------------------------------------------------------------------
#define F_QTILE 16384                    // 128 rows x 128B
#define F_KVTILE 8192                    // 64 rows x 128B
#define F_STAGE (4 * F_KVTILE)           // 32768
#define F_SMEM (2 * F_QTILE + 2 * F_STAGE)   // 98304

__global__ __launch_bounds__(128, 2)
void flash_mma_kernel()
{
    extern __shared__ char smem[];
    const uint32_t sb = s2u(smem);
    const int tid = threadIdx.x;
    const int lane = tid & 31;
    const int w = tid >> 5;
    const int bh = blockIdx.y;
    const int qb = blockIdx.x * 128;
    const int b = bh >> 4, h = bh & 15;

    const size_t bhbase = (size_t)bh * NN * HD;
    const __nv_bfloat16* Qhig = g_Qhi + bhbase + (size_t)qb * HD;
    const __nv_bfloat16* Qlog = g_Qlo + bhbase + (size_t)qb * HD;

    const uint32_t QHI = sb, QLO = sb + F_QTILE;

    // Prologue: load Q (2 tiles x 1024 chunks)
#pragma unroll
    for (int it = 0; it < 16; it++) {
        int idx = tid + it * 128;
        int m = idx >> 10;
        int rem = idx & 1023;
        int row = rem >> 3, c = rem & 7;
        const __nv_bfloat16* src = (m ? Qlog : Qhig) + row * HD + c * 8;
        CP16(tile_addr(sb + m * F_QTILE, row, c), src);
    }
    CPCOMMIT();

    auto issue_kv = [&](int kt) {
        const uint32_t stage = sb + 2 * F_QTILE + (kt & 1) * F_STAGE;
        const size_t kvoff = bhbase + (size_t)kt * 64 * HD;
#pragma unroll
        for (int it = 0; it < 16; it++) {
            int idx = tid + it * 128;
            int m = idx >> 9;
            int rem = idx & 511;
            int row = rem >> 3, c = rem & 7;
            const __nv_bfloat16* src =
                (m == 0 ? g_Khi : m == 1 ? g_Klo : m == 2 ? g_Vhi : g_Vlo)
                + kvoff + row * HD + c * 8;
            CP16(tile_addr(stage + m * F_KVTILE, row, c), src);
        }
        CPCOMMIT();
    };

    issue_kv(0);
    CPWAIT(0);
    __syncthreads();

    const int mi = lane >> 3;
    const int rw = lane & 7;

    float mm[2][2], ll[2][2];
    float o[2][8][4];
#pragma unroll
    for (int mt = 0; mt < 2; mt++) {
        mm[mt][0] = mm[mt][1] = -1e30f;
        ll[mt][0] = ll[mt][1] = 0.0f;
#pragma unroll
        for (int j = 0; j < 8; j++)
#pragma unroll
            for (int q = 0; q < 4; q++) o[mt][j][q] = 0.0f;
    }

    const float scale = 0.125f;

    for (int kt = 0; kt < 32; kt++) {
        __syncthreads();
        if (kt < 31) { issue_kv(kt + 1); CPWAIT(1); }
        else         { CPWAIT(0); }
        __syncthreads();

        const uint32_t stage = sb + 2 * F_QTILE + (kt & 1) * F_STAGE;
        const uint32_t KHI = stage, KLO = stage + F_KVTILE;
        const uint32_t VHI = stage + 2 * F_KVTILE, VLO = stage + 3 * F_KVTILE;

        // S = Q @ K^T (3-term split)
        float s[2][8][4];
#pragma unroll
        for (int mt = 0; mt < 2; mt++)
#pragma unroll
            for (int j = 0; j < 8; j++)
#pragma unroll
                for (int q = 0; q < 4; q++) s[mt][j][q] = 0.0f;

#pragma unroll
        for (int ks = 0; ks < 4; ks++) {
            uint32_t qh[2][4], ql[2][4];
#pragma unroll
            for (int mt = 0; mt < 2; mt++) {
                int row = w * 32 + mt * 16 + ((mi & 1) << 3) + rw;
                int ch = ks * 2 + (mi >> 1);
                ldmx4(qh[mt], tile_addr(QHI, row, ch));
                ldmx4(ql[mt], tile_addr(QLO, row, ch));
            }
#pragma unroll
            for (int jj = 0; jj < 4; jj++) {
                int brow = jj * 16 + ((mi >> 1) << 3) + rw;
                int bch = ks * 2 + (mi & 1);
                uint32_t khi[4], klo[4];
                ldmx4(khi, tile_addr(KHI, brow, bch));
                ldmx4(klo, tile_addr(KLO, brow, bch));
#pragma unroll
                for (int mt = 0; mt < 2; mt++) {
                    mma_bf16(s[mt][2 * jj],     qh[mt], khi[0], khi[1]);
                    mma_bf16(s[mt][2 * jj],     qh[mt], klo[0], klo[1]);
                    mma_bf16(s[mt][2 * jj],     ql[mt], khi[0], khi[1]);
                    mma_bf16(s[mt][2 * jj + 1], qh[mt], khi[2], khi[3]);
                    mma_bf16(s[mt][2 * jj + 1], qh[mt], klo[2], klo[3]);
                    mma_bf16(s[mt][2 * jj + 1], ql[mt], khi[2], khi[3]);
                }
            }
        }

        // online softmax per m-tile
#pragma unroll
        for (int mt = 0; mt < 2; mt++) {
            float rm0 = -1e30f, rm1 = -1e30f;
#pragma unroll
            for (int j = 0; j < 8; j++) {
#pragma unroll
                for (int q = 0; q < 4; q++) s[mt][j][q] *= scale;
                rm0 = fmaxf(rm0, fmaxf(s[mt][j][0], s[mt][j][1]));
                rm1 = fmaxf(rm1, fmaxf(s[mt][j][2], s[mt][j][3]));
            }
            rm0 = fmaxf(rm0, __shfl_xor_sync(0xffffffffu, rm0, 1));
            rm0 = fmaxf(rm0, __shfl_xor_sync(0xffffffffu, rm0, 2));
            rm1 = fmaxf(rm1, __shfl_xor_sync(0xffffffffu, rm1, 1));
            rm1 = fmaxf(rm1, __shfl_xor_sync(0xffffffffu, rm1, 2));

            float nm0 = fmaxf(mm[mt][0], rm0), nm1 = fmaxf(mm[mt][1], rm1);
            float f0 = __expf(mm[mt][0] - nm0), f1 = __expf(mm[mt][1] - nm1);
            mm[mt][0] = nm0; mm[mt][1] = nm1;
#pragma unroll
            for (int j = 0; j < 8; j++) {
                o[mt][j][0] *= f0; o[mt][j][1] *= f0;
                o[mt][j][2] *= f1; o[mt][j][3] *= f1;
            }

            float rs0 = 0.0f, rs1 = 0.0f;
#pragma unroll
            for (int j = 0; j < 8; j++) {
                s[mt][j][0] = __expf(s[mt][j][0] - nm0);
                s[mt][j][1] = __expf(s[mt][j][1] - nm0);
                s[mt][j][2] = __expf(s[mt][j][2] - nm1);
                s[mt][j][3] = __expf(s[mt][j][3] - nm1);
                rs0 += s[mt][j][0] + s[mt][j][1];
                rs1 += s[mt][j][2] + s[mt][j][3];
            }
            rs0 += __shfl_xor_sync(0xffffffffu, rs0, 1);
            rs0 += __shfl_xor_sync(0xffffffffu, rs0, 2);
            rs1 += __shfl_xor_sync(0xffffffffu, rs1, 1);
            rs1 += __shfl_xor_sync(0xffffffffu, rs1, 2);
            ll[mt][0] = ll[mt][0] * f0 + rs0;
            ll[mt][1] = ll[mt][1] * f1 + rs1;
        }

        // O += P @ V (3-term); P hi/lo packed per kk
#pragma unroll
        for (int kk = 0; kk < 4; kk++) {
            uint32_t pa[2][4], pl[2][4];
#pragma unroll
            for (int mt = 0; mt < 2; mt++) {
                pa[mt][0] = pack_bf16(s[mt][2 * kk][0],     s[mt][2 * kk][1]);
                pa[mt][1] = pack_bf16(s[mt][2 * kk][2],     s[mt][2 * kk][3]);
                pa[mt][2] = pack_bf16(s[mt][2 * kk + 1][0], s[mt][2 * kk + 1][1]);
                pa[mt][3] = pack_bf16(s[mt][2 * kk + 1][2], s[mt][2 * kk + 1][3]);
                pl[mt][0] = residual_pack(pa[mt][0], s[mt][2 * kk][0],     s[mt][2 * kk][1]);
                pl[mt][1] = residual_pack(pa[mt][1], s[mt][2 * kk][2],     s[mt][2 * kk][3]);
                pl[mt][2] = residual_pack(pa[mt][2], s[mt][2 * kk + 1][0], s[mt][2 * kk + 1][1]);
                pl[mt][3] = residual_pack(pa[mt][3], s[mt][2 * kk + 1][2], s[mt][2 * kk + 1][3]);
            }
#pragma unroll
            for (int jj = 0; jj < 4; jj++) {
                int vrow = kk * 16 + ((mi & 1) << 3) + rw;
                int vch = jj * 2 + (mi >> 1);
                uint32_t vh[4], vl[4];
                ldmx4t(vh, tile_addr(VHI, vrow, vch));
                ldmx4t(vl, tile_addr(VLO, vrow, vch));
#pragma unroll
                for (int mt = 0; mt < 2; mt++) {
                    mma_bf16(o[mt][2 * jj],     pa[mt], vh[0], vh[1]);
                    mma_bf16(o[mt][2 * jj],     pa[mt], vl[0], vl[1]);
                    mma_bf16(o[mt][2 * jj],     pl[mt], vh[0], vh[1]);
                    mma_bf16(o[mt][2 * jj + 1], pa[mt], vh[2], vh[3]);
                    mma_bf16(o[mt][2 * jj + 1], pa[mt], vl[2], vl[3]);
                    mma_bf16(o[mt][2 * jj + 1], pl[mt], vh[2], vh[3]);
                }
            }
        }
    }

    // Epilogue: AO[b*n][h*64+d] as bf16 hi/lo
#pragma unroll
    for (int mt = 0; mt < 2; mt++) {
        float inv0 = 1.0f / ll[mt][0], inv1 = 1.0f / ll[mt][1];
        int r0 = qb + w * 32 + mt * 16 + (lane >> 2);
        int r1 = r0 + 8;
        size_t row0 = (size_t)b * NN + r0;
        size_t row1 = (size_t)b * NN + r1;
#pragma unroll
        for (int j = 0; j < 8; j++) {
            int col = h * 64 + j * 8 + (lane & 3) * 2;
#pragma unroll
            for (int half = 0; half < 2; half++) {
                float v0 = o[mt][j][half * 2 + 0] * (half ? inv1 : inv0);
                float v1 = o[mt][j][half * 2 + 1] * (half ? inv1 : inv0);
                size_t ri = (half ? row1 : row0) * DD + col;
                uint32_t phi = pack_bf16(v0, v1);
                uint32_t plo = residual_pack(phi, v0, v1);
                *reinterpret_cast<uint32_t*>(&g_AOhi[ri]) = phi;
                *reinterpret_cast<uint32_t*>(&g_AOlo[ri]) = plo;
            }
        }
    }
}

// ----------------------------------------------------------------------------
extern "C" void kernel_launch(void* const* d_in, const int* in_sizes, int n_in,
                              void* d_out, int out_size)
{
    const float* x  = (const float*)d_in[0];
    const float* wq = (const float*)d_in[1];
    const float* wk = (const float*)d_in[2];
    const float* wv = (const float*)d_in[3];
    const float* wo = (const float*)d_in[4];
    const float* bo = (const float*)d_in[5];
    float* out = (float*)d_out;

    cudaFuncSetAttribute(gemm_mma_kernel,
                         cudaFuncAttributeMaxDynamicSharedMemorySize, G_SMEM);
    cudaFuncSetAttribute(flash_mma_kernel,
                         cudaFuncAttributeMaxDynamicSharedMemorySize, F_SMEM);

    // Split fp32 -> bf16 hi/lo
    split_x_kernel<<<4096, 256>>>(x);
    split_w_kernel<<<dim3(1024, 4), 256>>>(wq, wk, wv, wo);

    // QKV projections (z selects weight; epilogue writes Q/K/V bf16 hi/lo)
    gemm_mma_kernel<<<dim3(8, 16, 3), 256, G_SMEM>>>(0, nullptr, nullptr);

    // Attention (writes AO bf16 hi/lo)
    flash_mma_kernel<<<dim3(16, 32), 128, F_SMEM>>>();

    // Output projection + bias (fp32 out)
    gemm_mma_kernel<<<dim3(8, 16, 1), 256, G_SMEM>>>(1, out, bo);
}